// round 1
// baseline (speedup 1.0000x reference)
#include <cuda_runtime.h>
#include <math.h>

// Problem constants
#define BB   4
#define CCH  64
#define HH   256
#define WW   256
#define HWSZ (HH*WW)
#define DGRP 8
#define NTAP 9

// ---------------------------------------------------------------------------
// Scratch buffers (device globals; no allocation allowed in kernel_launch)
// ---------------------------------------------------------------------------
__device__ float g_warped[BB*CCH*HWSZ];
__device__ float g_feat0 [BB*CCH*HWSZ];
__device__ float g_tmp   [BB*CCH*HWSZ];
__device__ float g_feat  [BB*CCH*HWSZ];
__device__ float g_off   [BB*216*HWSZ];

// Transposed weights: [cin][tap][cout] (cout padded to CoutP)
__device__ float g_wT_fc [128*9*64];
__device__ float g_wT_c1 [64*9*64];
__device__ float g_wT_c2 [64*9*64];
__device__ float g_wT_c3 [64*9*64];
__device__ float g_wT_c4 [64*9*64];
__device__ float g_wT_c5 [64*9*64];
__device__ float g_wT_c6 [64*9*64];
__device__ float g_wT_off[64*9*256];      // Cout=216 padded to 256
__device__ float g_wT_dcn[9*64*64];       // [tap][cin][cout]

// ---------------------------------------------------------------------------
// Weight transposes (tiny, run each call; deterministic)
// ---------------------------------------------------------------------------
__global__ void transpose_w_kernel(const float* __restrict__ w, float* __restrict__ wT,
                                   int CIN, int Cout, int CoutP)
{
    int idx = blockIdx.x * 256 + threadIdx.x;
    int total = CIN * 9 * CoutP;
    if (idx >= total) return;
    int cout = idx % CoutP;
    int tap  = (idx / CoutP) % 9;
    int cin  = idx / (9 * CoutP);
    wT[idx] = (cout < Cout) ? w[(cout * CIN + cin) * 9 + tap] : 0.f;
}

__global__ void transpose_dcn_kernel(const float* __restrict__ w, float* __restrict__ wT)
{
    int idx = blockIdx.x * 256 + threadIdx.x;   // 9*64*64
    if (idx >= 9*64*64) return;
    int cout = idx % 64;
    int c    = (idx / 64) % 64;
    int k    = idx / (64 * 64);
    wT[idx] = w[(cout * 64 + c) * 9 + k];
}

// ---------------------------------------------------------------------------
// flow_warp: bilinear sample (zero padding) of supp at (x+fx, y+fy)
// ---------------------------------------------------------------------------
__global__ void warp_kernel(const float* __restrict__ supp,
                            const float* __restrict__ flow,
                            float* __restrict__ outw)
{
    int p = blockIdx.x * 256 + threadIdx.x;
    int b = blockIdx.y;
    if (p >= HWSZ) return;
    int y = p / WW, x = p % WW;
    float fx = flow[(b*2 + 0)*HWSZ + p];
    float fy = flow[(b*2 + 1)*HWSZ + p];
    float sy = (float)y + fy;
    float sx = (float)x + fx;
    float y0f = floorf(sy), x0f = floorf(sx);
    int iy0 = (int)y0f, ix0 = (int)x0f;
    int iy1 = iy0 + 1,  ix1 = ix0 + 1;
    float wy = sy - y0f, wx = sx - x0f;
    bool vy0 = ((unsigned)iy0 < HH), vy1 = ((unsigned)iy1 < HH);
    bool vx0 = ((unsigned)ix0 < WW), vx1 = ((unsigned)ix1 < WW);
    float w00 = (1.f - wy) * (1.f - wx) * ((vy0 && vx0) ? 1.f : 0.f);
    float w01 = (1.f - wy) * wx        * ((vy0 && vx1) ? 1.f : 0.f);
    float w10 = wy * (1.f - wx)        * ((vy1 && vx0) ? 1.f : 0.f);
    float w11 = wy * wx                * ((vy1 && vx1) ? 1.f : 0.f);
    int cy0 = min(max(iy0, 0), HH-1), cy1 = min(max(iy1, 0), HH-1);
    int cx0 = min(max(ix0, 0), WW-1), cx1 = min(max(ix1, 0), WW-1);
    int i00 = cy0*WW + cx0, i01 = cy0*WW + cx1;
    int i10 = cy1*WW + cx0, i11 = cy1*WW + cx1;
    const float* sb = supp + b*CCH*HWSZ;
    float*       ob = outw + b*CCH*HWSZ;
    #pragma unroll 8
    for (int c = 0; c < CCH; c++) {
        const float* ch = sb + c*HWSZ;
        ob[c*HWSZ + p] = w00*ch[i00] + w01*ch[i01] + w10*ch[i10] + w11*ch[i11];
    }
}

// ---------------------------------------------------------------------------
// Generic 3x3 conv, NCHW fp32.
//   block = 256 threads: cout = tid&63 (+ 64*chunk), pixel-group = tid>>6,
//   each thread computes 16 contiguous pixels of one row.
//   ACT: 0 none, 1 relu, 2 leaky-relu(0.1)
//   EPI: 0 store, 1 out = res + v, 2 out += 0.1*v
//   If CIN==128, cin<64 comes from in0, cin>=64 from in1 (fused concat).
// ---------------------------------------------------------------------------
template<int CIN, int DIL, int ACT, int EPI, int NCHUNK>
__global__ void __launch_bounds__(256, 2)
conv3x3_kernel(const float* __restrict__ in0, const float* __restrict__ in1,
               const float* __restrict__ wT, const float* __restrict__ bias,
               float* __restrict__ out, const float* __restrict__ res,
               int Cout, int CoutP)
{
    extern __shared__ float sIn[];
    const int TW  = 64 + 2*DIL;
    const int SEG = 16 + 2*DIL;
    int b     = blockIdx.z / NCHUNK;
    int chunk = blockIdx.z % NCHUNK;
    int y     = blockIdx.y;
    int x0    = blockIdx.x * 64;
    int tid   = threadIdx.x;

    // Cooperative load of the 3-row input tile (zero padded), all CIN channels
    int total = CIN * 3 * TW;
    for (int i = tid; i < total; i += 256) {
        int xx  = i % TW;
        int rr  = (i / TW) % 3;
        int cin = i / (3 * TW);
        int gy = y + (rr - 1) * DIL;
        int gx = x0 - DIL + xx;
        float v = 0.f;
        if ((unsigned)gy < HH && (unsigned)gx < WW) {
            const float* base = (cin < 64) ? in0 : in1;
            int cc = cin & 63;
            v = base[((b*64 + cc)*HH + gy)*WW + gx];
        }
        sIn[i] = v;
    }
    __syncthreads();

    int cout  = chunk * 64 + (tid & 63);
    int pg    = tid >> 6;
    int xbase = pg * 16;
    float bv = (cout < Cout) ? bias[cout] : 0.f;
    float acc[16];
    #pragma unroll
    for (int i = 0; i < 16; i++) acc[i] = bv;

    const float* wp = wT + cout;
    for (int cin = 0; cin < CIN; cin++) {
        const float* srowbase = sIn + cin * 3 * TW + xbase;
        #pragma unroll
        for (int r = 0; r < 3; r++) {
            float seg[SEG];
            const float* srow = srowbase + r * TW;
            #pragma unroll
            for (int i = 0; i < SEG; i++) seg[i] = srow[i];
            float w0 = wp[(cin*9 + r*3 + 0) * CoutP];
            float w1 = wp[(cin*9 + r*3 + 1) * CoutP];
            float w2 = wp[(cin*9 + r*3 + 2) * CoutP];
            #pragma unroll
            for (int px = 0; px < 16; px++) {
                acc[px] = fmaf(w0, seg[px],
                           fmaf(w1, seg[px + DIL],
                            fmaf(w2, seg[px + 2*DIL], acc[px])));
            }
        }
    }

    if (cout < Cout) {
        int ob = ((b*Cout + cout)*HH + y)*WW + x0 + xbase;
        #pragma unroll
        for (int px = 0; px < 16; px++) {
            float v = acc[px];
            if (ACT == 1) v = fmaxf(v, 0.f);
            else if (ACT == 2) v = (v > 0.f) ? v : 0.1f * v;
            if (EPI == 0)      out[ob + px] = v;
            else if (EPI == 1) out[ob + px] = res[ob + px] + v;
            else               out[ob + px] = out[ob + px] + 0.1f * v;
        }
    }
}

// ---------------------------------------------------------------------------
// Modulated deformable conv (DG=8 offset groups, full 64x64 weight, 3x3)
// Per tap k: 512 (pixel,group) sampling tasks fill sS[64ch][64px] in smem,
// then a register-blocked rank-64 update into 64cout x 16px accumulators.
// ---------------------------------------------------------------------------
__global__ void __launch_bounds__(256, 2)
dcn_kernel(const float* __restrict__ supp, const float* __restrict__ off,
           const float* __restrict__ flow, const float* __restrict__ wT,
           const float* __restrict__ bias, float* __restrict__ out)
{
    __shared__ __align__(16) float sS[64*64];
    int b  = blockIdx.z;
    int y  = blockIdx.y;
    int x0 = blockIdx.x * 64;
    int tid  = threadIdx.x;
    int cout = tid & 63;
    int pg   = tid >> 6;

    float bv = bias[cout];
    float acc[16];
    #pragma unroll
    for (int i = 0; i < 16; i++) acc[i] = bv;

    const float* fxp  = flow + (b*2 + 0)*HWSZ + y*WW + x0;
    const float* fyp  = flow + (b*2 + 1)*HWSZ + y*WW + x0;
    const float* offb = off  + b*216*HWSZ + y*WW + x0;

    for (int k = 0; k < NTAP; k++) {
        int ki = k / 3, kj = k % 3;
        __syncthreads();   // protect sS from previous iteration's readers
        #pragma unroll
        for (int it = 0; it < 2; it++) {
            int t  = tid + 256 * it;
            int px = t & 63;
            int g  = t >> 6;
            int cdy = g*18 + k*2;
            float rawdy = offb[cdy        *HWSZ + px];
            float rawdx = offb[(cdy + 1)  *HWSZ + px];
            float rawm  = offb[(144 + g*9 + k)*HWSZ + px];
            float fx = fxp[px], fy = fyp[px];
            // offset channel c gets +flow_x if c<72 else +flow_y (reference quirk)
            float ady = 25.f * tanhf(rawdy) + ((cdy     < 72) ? fx : fy);
            float adx = 25.f * tanhf(rawdx) + ((cdy + 1 < 72) ? fx : fy);
            float m   = 1.f / (1.f + expf(-rawm));
            float sy = (float)y        + (float)(ki - 1) + ady;
            float sx = (float)(x0 + px)+ (float)(kj - 1) + adx;
            float y0f = floorf(sy), x0f = floorf(sx);
            int iy0 = (int)y0f, ix0 = (int)x0f;
            int iy1 = iy0 + 1,  ix1 = ix0 + 1;
            float wy = sy - y0f, wx = sx - x0f;
            bool vy0 = ((unsigned)iy0 < HH), vy1 = ((unsigned)iy1 < HH);
            bool vx0 = ((unsigned)ix0 < WW), vx1 = ((unsigned)ix1 < WW);
            float w00 = (1.f - wy)*(1.f - wx) * ((vy0 && vx0) ? 1.f : 0.f) * m;
            float w01 = (1.f - wy)*wx         * ((vy0 && vx1) ? 1.f : 0.f) * m;
            float w10 = wy*(1.f - wx)         * ((vy1 && vx0) ? 1.f : 0.f) * m;
            float w11 = wy*wx                 * ((vy1 && vx1) ? 1.f : 0.f) * m;
            int cy0 = min(max(iy0, 0), HH-1), cy1 = min(max(iy1, 0), HH-1);
            int cx0 = min(max(ix0, 0), WW-1), cx1 = min(max(ix1, 0), WW-1);
            int i00 = cy0*WW + cx0, i01 = cy0*WW + cx1;
            int i10 = cy1*WW + cx0, i11 = cy1*WW + cx1;
            const float* sb = supp + (b*64 + g*8)*HWSZ;
            #pragma unroll
            for (int c = 0; c < 8; c++) {
                const float* ch = sb + c*HWSZ;
                float v = w00*ch[i00] + w01*ch[i01] + w10*ch[i10] + w11*ch[i11];
                sS[(g*8 + c)*64 + px] = v;
            }
        }
        __syncthreads();

        const float* wk = wT + k*64*64 + cout;
        #pragma unroll 4
        for (int c = 0; c < 64; c++) {
            float wv = wk[c*64];
            const float4* sr = (const float4*)(sS + c*64 + pg*16);
            #pragma unroll
            for (int q = 0; q < 4; q++) {
                float4 v = sr[q];
                acc[q*4+0] = fmaf(wv, v.x, acc[q*4+0]);
                acc[q*4+1] = fmaf(wv, v.y, acc[q*4+1]);
                acc[q*4+2] = fmaf(wv, v.z, acc[q*4+2]);
                acc[q*4+3] = fmaf(wv, v.w, acc[q*4+3]);
            }
        }
    }

    int ob = ((b*64 + cout)*HH + y)*WW + x0 + pg*16;
    #pragma unroll
    for (int px = 0; px < 16; px++) out[ob + px] = acc[px];
}

// ---------------------------------------------------------------------------
// Launch
// ---------------------------------------------------------------------------
extern "C" void kernel_launch(void* const* d_in, const int* in_sizes, int n_in,
                              void* d_out, int out_size)
{
    const float* ref   = (const float*)d_in[0];
    const float* supp  = (const float*)d_in[1];
    const float* flow  = (const float*)d_in[2];
    const float* fc_w  = (const float*)d_in[3];
    const float* fc_b  = (const float*)d_in[4];
    const float* cw[6], *cb[6];
    for (int i = 0; i < 6; i++) {
        cw[i] = (const float*)d_in[5 + 2*i];
        cb[i] = (const float*)d_in[6 + 2*i];
    }
    const float* off_w = (const float*)d_in[17];
    const float* off_b = (const float*)d_in[18];
    const float* dcn_w = (const float*)d_in[19];
    const float* dcn_b = (const float*)d_in[20];
    float* out = (float*)d_out;

    float *warped, *feat0, *tmp, *feat, *offbuf;
    float *wT_fc, *wT_c1, *wT_c2, *wT_c3, *wT_c4, *wT_c5, *wT_c6, *wT_off, *wT_dcn;
    cudaGetSymbolAddress((void**)&warped, g_warped);
    cudaGetSymbolAddress((void**)&feat0,  g_feat0);
    cudaGetSymbolAddress((void**)&tmp,    g_tmp);
    cudaGetSymbolAddress((void**)&feat,   g_feat);
    cudaGetSymbolAddress((void**)&offbuf, g_off);
    cudaGetSymbolAddress((void**)&wT_fc,  g_wT_fc);
    cudaGetSymbolAddress((void**)&wT_c1,  g_wT_c1);
    cudaGetSymbolAddress((void**)&wT_c2,  g_wT_c2);
    cudaGetSymbolAddress((void**)&wT_c3,  g_wT_c3);
    cudaGetSymbolAddress((void**)&wT_c4,  g_wT_c4);
    cudaGetSymbolAddress((void**)&wT_c5,  g_wT_c5);
    cudaGetSymbolAddress((void**)&wT_c6,  g_wT_c6);
    cudaGetSymbolAddress((void**)&wT_off, g_wT_off);
    cudaGetSymbolAddress((void**)&wT_dcn, g_wT_dcn);

    // Dynamic smem opt-in (idempotent)
    const int SM_FC = 128*3*(64+2)*4;   // 101376
    const int SM_D1 = 64*3*(64+2)*4;    // 50688
    const int SM_D2 = 64*3*(64+4)*4;    // 52224
    const int SM_D4 = 64*3*(64+8)*4;    // 55296
    cudaFuncSetAttribute((const void*)conv3x3_kernel<128,1,2,0,1>, cudaFuncAttributeMaxDynamicSharedMemorySize, SM_FC);
    cudaFuncSetAttribute((const void*)conv3x3_kernel<64,1,1,0,1>,  cudaFuncAttributeMaxDynamicSharedMemorySize, SM_D1);
    cudaFuncSetAttribute((const void*)conv3x3_kernel<64,1,1,1,1>,  cudaFuncAttributeMaxDynamicSharedMemorySize, SM_D1);
    cudaFuncSetAttribute((const void*)conv3x3_kernel<64,2,1,0,1>,  cudaFuncAttributeMaxDynamicSharedMemorySize, SM_D2);
    cudaFuncSetAttribute((const void*)conv3x3_kernel<64,2,1,2,1>,  cudaFuncAttributeMaxDynamicSharedMemorySize, SM_D2);
    cudaFuncSetAttribute((const void*)conv3x3_kernel<64,4,1,2,1>,  cudaFuncAttributeMaxDynamicSharedMemorySize, SM_D4);
    cudaFuncSetAttribute((const void*)conv3x3_kernel<64,1,0,0,4>,  cudaFuncAttributeMaxDynamicSharedMemorySize, SM_D1);

    // Weight transposes
    {
        int t;
        t = 128*9*64;  transpose_w_kernel<<<(t+255)/256, 256>>>(fc_w,  wT_fc, 128, 64, 64);
        t = 64*9*64;
        transpose_w_kernel<<<(t+255)/256, 256>>>(cw[0], wT_c1, 64, 64, 64);
        transpose_w_kernel<<<(t+255)/256, 256>>>(cw[1], wT_c2, 64, 64, 64);
        transpose_w_kernel<<<(t+255)/256, 256>>>(cw[2], wT_c3, 64, 64, 64);
        transpose_w_kernel<<<(t+255)/256, 256>>>(cw[3], wT_c4, 64, 64, 64);
        transpose_w_kernel<<<(t+255)/256, 256>>>(cw[4], wT_c5, 64, 64, 64);
        transpose_w_kernel<<<(t+255)/256, 256>>>(cw[5], wT_c6, 64, 64, 64);
        t = 64*9*256;  transpose_w_kernel<<<(t+255)/256, 256>>>(off_w, wT_off, 64, 216, 256);
        t = 9*64*64;   transpose_dcn_kernel<<<(t+255)/256, 256>>>(dcn_w, wT_dcn);
    }

    // 1. flow warp
    warp_kernel<<<dim3(HWSZ/256, BB), 256>>>(supp, flow, warped);

    dim3 cgrid(WW/64, HH, BB);
    // 2. fc conv: concat(warped, ref) -> feat0, lrelu 0.1
    conv3x3_kernel<128,1,2,0,1><<<cgrid, 256, SM_FC>>>(warped, ref, wT_fc, fc_b, feat0, nullptr, 64, 64);
    // 3-4. b1 branch
    conv3x3_kernel<64,1,1,0,1><<<cgrid, 256, SM_D1>>>(feat0, feat0, wT_c1, cb[0], tmp, nullptr, 64, 64);
    conv3x3_kernel<64,1,1,1,1><<<cgrid, 256, SM_D1>>>(tmp, tmp, wT_c2, cb[1], feat, feat0, 64, 64);
    // 5-6. b2 branch (feat += 0.1*b2)
    conv3x3_kernel<64,2,1,0,1><<<cgrid, 256, SM_D2>>>(feat0, feat0, wT_c3, cb[2], tmp, nullptr, 64, 64);
    conv3x3_kernel<64,2,1,2,1><<<cgrid, 256, SM_D2>>>(tmp, tmp, wT_c4, cb[3], feat, nullptr, 64, 64);
    // 7-8. b3 branch (feat += 0.1*b3)
    conv3x3_kernel<64,2,1,0,1><<<cgrid, 256, SM_D2>>>(feat0, feat0, wT_c5, cb[4], tmp, nullptr, 64, 64);
    conv3x3_kernel<64,4,1,2,1><<<cgrid, 256, SM_D4>>>(tmp, tmp, wT_c6, cb[5], feat, nullptr, 64, 64);
    // 9. offset/mask conv: 64 -> 216 (4 chunks of 64 couts, padded weights)
    dim3 ogrid(WW/64, HH, BB*4);
    conv3x3_kernel<64,1,0,0,4><<<ogrid, 256, SM_D1>>>(feat, feat, wT_off, off_b, offbuf, nullptr, 216, 256);
    // 10. modulated deformable conv
    dcn_kernel<<<cgrid, 256>>>(supp, offbuf, flow, wT_dcn, dcn_b, out);
}

// round 2
// speedup vs baseline: 1.0000x; 1.0000x over previous
#include <cuda_runtime.h>
#include <math.h>

// Problem constants
#define BB   4
#define CCH  64
#define HH   256
#define WW   256
#define HWSZ (HH*WW)
#define DGRP 8
#define NTAP 9

// ---------------------------------------------------------------------------
// Scratch buffers (device globals; no allocation allowed in kernel_launch)
// ---------------------------------------------------------------------------
__device__ float g_warped[BB*CCH*HWSZ];
__device__ float g_feat0 [BB*CCH*HWSZ];
__device__ float g_tmp   [BB*CCH*HWSZ];
__device__ float g_feat  [BB*CCH*HWSZ];
__device__ float g_off   [BB*216*HWSZ];

// Transposed weights: [cin][tap][cout] (cout padded to CoutP)
__device__ float g_wT_fc [128*9*64];
__device__ float g_wT_c1 [64*9*64];
__device__ float g_wT_c2 [64*9*64];
__device__ float g_wT_c3 [64*9*64];
__device__ float g_wT_c4 [64*9*64];
__device__ float g_wT_c5 [64*9*64];
__device__ float g_wT_c6 [64*9*64];
__device__ float g_wT_off[64*9*256];      // Cout=216 padded to 256
__device__ float g_wT_dcn[9*64*64];       // [tap][cin][cout]

// ---------------------------------------------------------------------------
// Weight transposes (tiny, run each call; deterministic)
// ---------------------------------------------------------------------------
__global__ void transpose_w_kernel(const float* __restrict__ w, float* __restrict__ wT,
                                   int CIN, int Cout, int CoutP)
{
    int idx = blockIdx.x * 256 + threadIdx.x;
    int total = CIN * 9 * CoutP;
    if (idx >= total) return;
    int cout = idx % CoutP;
    int tap  = (idx / CoutP) % 9;
    int cin  = idx / (9 * CoutP);
    wT[idx] = (cout < Cout) ? w[(cout * CIN + cin) * 9 + tap] : 0.f;
}

__global__ void transpose_dcn_kernel(const float* __restrict__ w, float* __restrict__ wT)
{
    int idx = blockIdx.x * 256 + threadIdx.x;   // 9*64*64
    if (idx >= 9*64*64) return;
    int cout = idx % 64;
    int c    = (idx / 64) % 64;
    int k    = idx / (64 * 64);
    wT[idx] = w[(cout * 64 + c) * 9 + k];
}

// ---------------------------------------------------------------------------
// flow_warp: bilinear sample (zero padding) of supp at (x+fx, y+fy)
// ---------------------------------------------------------------------------
__global__ void warp_kernel(const float* __restrict__ supp,
                            const float* __restrict__ flow,
                            float* __restrict__ outw)
{
    int p = blockIdx.x * 256 + threadIdx.x;
    int b = blockIdx.y;
    if (p >= HWSZ) return;
    int y = p / WW, x = p % WW;
    float fx = flow[(b*2 + 0)*HWSZ + p];
    float fy = flow[(b*2 + 1)*HWSZ + p];
    float sy = (float)y + fy;
    float sx = (float)x + fx;
    float y0f = floorf(sy), x0f = floorf(sx);
    int iy0 = (int)y0f, ix0 = (int)x0f;
    int iy1 = iy0 + 1,  ix1 = ix0 + 1;
    float wy = sy - y0f, wx = sx - x0f;
    bool vy0 = ((unsigned)iy0 < HH), vy1 = ((unsigned)iy1 < HH);
    bool vx0 = ((unsigned)ix0 < WW), vx1 = ((unsigned)ix1 < WW);
    float w00 = (1.f - wy) * (1.f - wx) * ((vy0 && vx0) ? 1.f : 0.f);
    float w01 = (1.f - wy) * wx        * ((vy0 && vx1) ? 1.f : 0.f);
    float w10 = wy * (1.f - wx)        * ((vy1 && vx0) ? 1.f : 0.f);
    float w11 = wy * wx                * ((vy1 && vx1) ? 1.f : 0.f);
    int cy0 = min(max(iy0, 0), HH-1), cy1 = min(max(iy1, 0), HH-1);
    int cx0 = min(max(ix0, 0), WW-1), cx1 = min(max(ix1, 0), WW-1);
    int i00 = cy0*WW + cx0, i01 = cy0*WW + cx1;
    int i10 = cy1*WW + cx0, i11 = cy1*WW + cx1;
    const float* sb = supp + b*CCH*HWSZ;
    float*       ob = outw + b*CCH*HWSZ;
    #pragma unroll 8
    for (int c = 0; c < CCH; c++) {
        const float* ch = sb + c*HWSZ;
        ob[c*HWSZ + p] = w00*ch[i00] + w01*ch[i01] + w10*ch[i10] + w11*ch[i11];
    }
}

// ---------------------------------------------------------------------------
// Generic 3x3 conv, NCHW fp32.
//   block = 256 threads: cout = tid&63 (+ 64*chunk), pixel-group = tid>>6,
//   each thread computes 16 contiguous pixels of one row.
//   ACT: 0 none, 1 relu, 2 leaky-relu(0.1)
//   EPI: 0 store, 1 out = res + v, 2 out += 0.1*v
//   If CIN==128, cin<64 comes from in0, cin>=64 from in1 (fused concat).
// ---------------------------------------------------------------------------
template<int CIN, int DIL, int ACT, int EPI, int NCHUNK>
__global__ void __launch_bounds__(256, 2)
conv3x3_kernel(const float* __restrict__ in0, const float* __restrict__ in1,
               const float* __restrict__ wT, const float* __restrict__ bias,
               float* __restrict__ out, const float* __restrict__ res,
               int Cout, int CoutP)
{
    extern __shared__ float sIn[];
    const int TW  = 64 + 2*DIL;
    const int SEG = 16 + 2*DIL;
    int b     = blockIdx.z / NCHUNK;
    int chunk = blockIdx.z % NCHUNK;
    int y     = blockIdx.y;
    int x0    = blockIdx.x * 64;
    int tid   = threadIdx.x;

    // Cooperative load of the 3-row input tile (zero padded), all CIN channels
    int total = CIN * 3 * TW;
    for (int i = tid; i < total; i += 256) {
        int xx  = i % TW;
        int rr  = (i / TW) % 3;
        int cin = i / (3 * TW);
        int gy = y + (rr - 1) * DIL;
        int gx = x0 - DIL + xx;
        float v = 0.f;
        if ((unsigned)gy < HH && (unsigned)gx < WW) {
            const float* base = (cin < 64) ? in0 : in1;
            int cc = cin & 63;
            v = base[((b*64 + cc)*HH + gy)*WW + gx];
        }
        sIn[i] = v;
    }
    __syncthreads();

    int cout  = chunk * 64 + (tid & 63);
    int pg    = tid >> 6;
    int xbase = pg * 16;
    float bv = (cout < Cout) ? bias[cout] : 0.f;
    float acc[16];
    #pragma unroll
    for (int i = 0; i < 16; i++) acc[i] = bv;

    const float* wp = wT + cout;
    for (int cin = 0; cin < CIN; cin++) {
        const float* srowbase = sIn + cin * 3 * TW + xbase;
        #pragma unroll
        for (int r = 0; r < 3; r++) {
            float seg[SEG];
            const float* srow = srowbase + r * TW;
            #pragma unroll
            for (int i = 0; i < SEG; i++) seg[i] = srow[i];
            float w0 = wp[(cin*9 + r*3 + 0) * CoutP];
            float w1 = wp[(cin*9 + r*3 + 1) * CoutP];
            float w2 = wp[(cin*9 + r*3 + 2) * CoutP];
            #pragma unroll
            for (int px = 0; px < 16; px++) {
                acc[px] = fmaf(w0, seg[px],
                           fmaf(w1, seg[px + DIL],
                            fmaf(w2, seg[px + 2*DIL], acc[px])));
            }
        }
    }

    if (cout < Cout) {
        int ob = ((b*Cout + cout)*HH + y)*WW + x0 + xbase;
        #pragma unroll
        for (int px = 0; px < 16; px++) {
            float v = acc[px];
            if (ACT == 1) v = fmaxf(v, 0.f);
            else if (ACT == 2) v = (v > 0.f) ? v : 0.1f * v;
            if (EPI == 0)      out[ob + px] = v;
            else if (EPI == 1) out[ob + px] = res[ob + px] + v;
            else               out[ob + px] = out[ob + px] + 0.1f * v;
        }
    }
}

// ---------------------------------------------------------------------------
// Modulated deformable conv (DG=8 offset groups, full 64x64 weight, 3x3)
// Per tap k: 512 (pixel,group) sampling tasks fill sS[64ch][64px] in smem,
// then a register-blocked rank-64 update into 64cout x 16px accumulators.
// ---------------------------------------------------------------------------
__global__ void __launch_bounds__(256, 2)
dcn_kernel(const float* __restrict__ supp, const float* __restrict__ off,
           const float* __restrict__ flow, const float* __restrict__ wT,
           const float* __restrict__ bias, float* __restrict__ out)
{
    __shared__ __align__(16) float sS[64*64];
    int b  = blockIdx.z;
    int y  = blockIdx.y;
    int x0 = blockIdx.x * 64;
    int tid  = threadIdx.x;
    int cout = tid & 63;
    int pg   = tid >> 6;

    float bv = bias[cout];
    float acc[16];
    #pragma unroll
    for (int i = 0; i < 16; i++) acc[i] = bv;

    const float* fxp  = flow + (b*2 + 0)*HWSZ + y*WW + x0;
    const float* fyp  = flow + (b*2 + 1)*HWSZ + y*WW + x0;
    const float* offb = off  + b*216*HWSZ + y*WW + x0;

    for (int k = 0; k < NTAP; k++) {
        int ki = k / 3, kj = k % 3;
        __syncthreads();   // protect sS from previous iteration's readers
        #pragma unroll
        for (int it = 0; it < 2; it++) {
            int t  = tid + 256 * it;
            int px = t & 63;
            int g  = t >> 6;
            int cdy = g*18 + k*2;
            float rawdy = offb[cdy        *HWSZ + px];
            float rawdx = offb[(cdy + 1)  *HWSZ + px];
            float rawm  = offb[(144 + g*9 + k)*HWSZ + px];
            float fx = fxp[px], fy = fyp[px];
            // offset channel c gets +flow_x if c<72 else +flow_y (reference quirk)
            float ady = 25.f * tanhf(rawdy) + ((cdy     < 72) ? fx : fy);
            float adx = 25.f * tanhf(rawdx) + ((cdy + 1 < 72) ? fx : fy);
            float m   = 1.f / (1.f + expf(-rawm));
            float sy = (float)y        + (float)(ki - 1) + ady;
            float sx = (float)(x0 + px)+ (float)(kj - 1) + adx;
            float y0f = floorf(sy), x0f = floorf(sx);
            int iy0 = (int)y0f, ix0 = (int)x0f;
            int iy1 = iy0 + 1,  ix1 = ix0 + 1;
            float wy = sy - y0f, wx = sx - x0f;
            bool vy0 = ((unsigned)iy0 < HH), vy1 = ((unsigned)iy1 < HH);
            bool vx0 = ((unsigned)ix0 < WW), vx1 = ((unsigned)ix1 < WW);
            float w00 = (1.f - wy)*(1.f - wx) * ((vy0 && vx0) ? 1.f : 0.f) * m;
            float w01 = (1.f - wy)*wx         * ((vy0 && vx1) ? 1.f : 0.f) * m;
            float w10 = wy*(1.f - wx)         * ((vy1 && vx0) ? 1.f : 0.f) * m;
            float w11 = wy*wx                 * ((vy1 && vx1) ? 1.f : 0.f) * m;
            int cy0 = min(max(iy0, 0), HH-1), cy1 = min(max(iy1, 0), HH-1);
            int cx0 = min(max(ix0, 0), WW-1), cx1 = min(max(ix1, 0), WW-1);
            int i00 = cy0*WW + cx0, i01 = cy0*WW + cx1;
            int i10 = cy1*WW + cx0, i11 = cy1*WW + cx1;
            const float* sb = supp + (b*64 + g*8)*HWSZ;
            #pragma unroll
            for (int c = 0; c < 8; c++) {
                const float* ch = sb + c*HWSZ;
                float v = w00*ch[i00] + w01*ch[i01] + w10*ch[i10] + w11*ch[i11];
                sS[(g*8 + c)*64 + px] = v;
            }
        }
        __syncthreads();

        const float* wk = wT + k*64*64 + cout;
        #pragma unroll 4
        for (int c = 0; c < 64; c++) {
            float wv = wk[c*64];
            const float4* sr = (const float4*)(sS + c*64 + pg*16);
            #pragma unroll
            for (int q = 0; q < 4; q++) {
                float4 v = sr[q];
                acc[q*4+0] = fmaf(wv, v.x, acc[q*4+0]);
                acc[q*4+1] = fmaf(wv, v.y, acc[q*4+1]);
                acc[q*4+2] = fmaf(wv, v.z, acc[q*4+2]);
                acc[q*4+3] = fmaf(wv, v.w, acc[q*4+3]);
            }
        }
    }

    int ob = ((b*64 + cout)*HH + y)*WW + x0 + pg*16;
    #pragma unroll
    for (int px = 0; px < 16; px++) out[ob + px] = acc[px];
}

// ---------------------------------------------------------------------------
// Launch
// ---------------------------------------------------------------------------
extern "C" void kernel_launch(void* const* d_in, const int* in_sizes, int n_in,
                              void* d_out, int out_size)
{
    const float* ref   = (const float*)d_in[0];
    const float* supp  = (const float*)d_in[1];
    const float* flow  = (const float*)d_in[2];
    const float* fc_w  = (const float*)d_in[3];
    const float* fc_b  = (const float*)d_in[4];
    const float* cw[6], *cb[6];
    for (int i = 0; i < 6; i++) {
        cw[i] = (const float*)d_in[5 + 2*i];
        cb[i] = (const float*)d_in[6 + 2*i];
    }
    const float* off_w = (const float*)d_in[17];
    const float* off_b = (const float*)d_in[18];
    const float* dcn_w = (const float*)d_in[19];
    const float* dcn_b = (const float*)d_in[20];
    float* out = (float*)d_out;

    float *warped, *feat0, *tmp, *feat, *offbuf;
    float *wT_fc, *wT_c1, *wT_c2, *wT_c3, *wT_c4, *wT_c5, *wT_c6, *wT_off, *wT_dcn;
    cudaGetSymbolAddress((void**)&warped, g_warped);
    cudaGetSymbolAddress((void**)&feat0,  g_feat0);
    cudaGetSymbolAddress((void**)&tmp,    g_tmp);
    cudaGetSymbolAddress((void**)&feat,   g_feat);
    cudaGetSymbolAddress((void**)&offbuf, g_off);
    cudaGetSymbolAddress((void**)&wT_fc,  g_wT_fc);
    cudaGetSymbolAddress((void**)&wT_c1,  g_wT_c1);
    cudaGetSymbolAddress((void**)&wT_c2,  g_wT_c2);
    cudaGetSymbolAddress((void**)&wT_c3,  g_wT_c3);
    cudaGetSymbolAddress((void**)&wT_c4,  g_wT_c4);
    cudaGetSymbolAddress((void**)&wT_c5,  g_wT_c5);
    cudaGetSymbolAddress((void**)&wT_c6,  g_wT_c6);
    cudaGetSymbolAddress((void**)&wT_off, g_wT_off);
    cudaGetSymbolAddress((void**)&wT_dcn, g_wT_dcn);

    // Dynamic smem opt-in (idempotent)
    const int SM_FC = 128*3*(64+2)*4;   // 101376
    const int SM_D1 = 64*3*(64+2)*4;    // 50688
    const int SM_D2 = 64*3*(64+4)*4;    // 52224
    const int SM_D4 = 64*3*(64+8)*4;    // 55296
    cudaFuncSetAttribute((const void*)conv3x3_kernel<128,1,2,0,1>, cudaFuncAttributeMaxDynamicSharedMemorySize, SM_FC);
    cudaFuncSetAttribute((const void*)conv3x3_kernel<64,1,1,0,1>,  cudaFuncAttributeMaxDynamicSharedMemorySize, SM_D1);
    cudaFuncSetAttribute((const void*)conv3x3_kernel<64,1,1,1,1>,  cudaFuncAttributeMaxDynamicSharedMemorySize, SM_D1);
    cudaFuncSetAttribute((const void*)conv3x3_kernel<64,2,1,0,1>,  cudaFuncAttributeMaxDynamicSharedMemorySize, SM_D2);
    cudaFuncSetAttribute((const void*)conv3x3_kernel<64,2,1,2,1>,  cudaFuncAttributeMaxDynamicSharedMemorySize, SM_D2);
    cudaFuncSetAttribute((const void*)conv3x3_kernel<64,4,1,2,1>,  cudaFuncAttributeMaxDynamicSharedMemorySize, SM_D4);
    cudaFuncSetAttribute((const void*)conv3x3_kernel<64,1,0,0,4>,  cudaFuncAttributeMaxDynamicSharedMemorySize, SM_D1);

    // Weight transposes
    {
        int t;
        t = 128*9*64;  transpose_w_kernel<<<(t+255)/256, 256>>>(fc_w,  wT_fc, 128, 64, 64);
        t = 64*9*64;
        transpose_w_kernel<<<(t+255)/256, 256>>>(cw[0], wT_c1, 64, 64, 64);
        transpose_w_kernel<<<(t+255)/256, 256>>>(cw[1], wT_c2, 64, 64, 64);
        transpose_w_kernel<<<(t+255)/256, 256>>>(cw[2], wT_c3, 64, 64, 64);
        transpose_w_kernel<<<(t+255)/256, 256>>>(cw[3], wT_c4, 64, 64, 64);
        transpose_w_kernel<<<(t+255)/256, 256>>>(cw[4], wT_c5, 64, 64, 64);
        transpose_w_kernel<<<(t+255)/256, 256>>>(cw[5], wT_c6, 64, 64, 64);
        t = 64*9*256;  transpose_w_kernel<<<(t+255)/256, 256>>>(off_w, wT_off, 64, 216, 256);
        t = 9*64*64;   transpose_dcn_kernel<<<(t+255)/256, 256>>>(dcn_w, wT_dcn);
    }

    // 1. flow warp
    warp_kernel<<<dim3(HWSZ/256, BB), 256>>>(supp, flow, warped);

    dim3 cgrid(WW/64, HH, BB);
    // 2. fc conv: concat(warped, ref) -> feat0, lrelu 0.1
    conv3x3_kernel<128,1,2,0,1><<<cgrid, 256, SM_FC>>>(warped, ref, wT_fc, fc_b, feat0, nullptr, 64, 64);
    // 3-4. b1 branch
    conv3x3_kernel<64,1,1,0,1><<<cgrid, 256, SM_D1>>>(feat0, feat0, wT_c1, cb[0], tmp, nullptr, 64, 64);
    conv3x3_kernel<64,1,1,1,1><<<cgrid, 256, SM_D1>>>(tmp, tmp, wT_c2, cb[1], feat, feat0, 64, 64);
    // 5-6. b2 branch (feat += 0.1*b2)
    conv3x3_kernel<64,2,1,0,1><<<cgrid, 256, SM_D2>>>(feat0, feat0, wT_c3, cb[2], tmp, nullptr, 64, 64);
    conv3x3_kernel<64,2,1,2,1><<<cgrid, 256, SM_D2>>>(tmp, tmp, wT_c4, cb[3], feat, nullptr, 64, 64);
    // 7-8. b3 branch (feat += 0.1*b3)
    conv3x3_kernel<64,2,1,0,1><<<cgrid, 256, SM_D2>>>(feat0, feat0, wT_c5, cb[4], tmp, nullptr, 64, 64);
    conv3x3_kernel<64,4,1,2,1><<<cgrid, 256, SM_D4>>>(tmp, tmp, wT_c6, cb[5], feat, nullptr, 64, 64);
    // 9. offset/mask conv: 64 -> 216 (4 chunks of 64 couts, padded weights)
    dim3 ogrid(WW/64, HH, BB*4);
    conv3x3_kernel<64,1,0,0,4><<<ogrid, 256, SM_D1>>>(feat, feat, wT_off, off_b, offbuf, nullptr, 216, 256);
    // 10. modulated deformable conv
    dcn_kernel<<<cgrid, 256>>>(supp, offbuf, flow, wT_dcn, dcn_b, out);
}